// round 4
// baseline (speedup 1.0000x reference)
#include <cuda_runtime.h>

#define NEGF (-1000000000.0f)
#define FULLMASK 0xffffffffu

// Scratch (device globals — no allocation allowed)
__device__ float g_pot[64 * 128 * 128];   // 4 MB: label/augment-maxed span potentials
__device__ float g_goldpart[4096];        // per-block gold partials (64 blocks per batch)
__device__ float g_margin[64];            // per-batch relu(pred - gold)

// ---------------------------------------------------------------------------
// Kernel 1: pot + gold partials. Thread-per-cell, branchless, no shuffles.
// Each thread: 8x LDG.128 (contiguous 128B cell), register max + gold select.
// Grid: 4096 blocks x 256 threads = 1,048,576 cells (64 blocks per batch).
// ---------------------------------------------------------------------------
__global__ void pot_kernel(const float* __restrict__ logits,
                           const int* __restrict__ labels) {
    __shared__ float gred[256];

    int gcell = blockIdx.x * 256 + threadIdx.x;
    int lab = labels[gcell];
    if (lab < 0) lab = 0;                   // jnp.maximum(labels, 0)

    const float4* lg = reinterpret_cast<const float4*>(logits) + (size_t)gcell * 8;

    float acc = NEGF, v0 = 0.0f, vl = 0.0f;
    #pragma unroll
    for (int c = 0; c < 8; ++c) {
        float4 f = lg[c];
        int l0 = c * 4;
        if (c == 0) v0 = f.x;
        acc = fmaxf(acc, f.x + (float)((l0 + 0) != lab));
        acc = fmaxf(acc, f.y + (float)((l0 + 1) != lab));
        acc = fmaxf(acc, f.z + (float)((l0 + 2) != lab));
        acc = fmaxf(acc, f.w + (float)((l0 + 3) != lab));
        vl = ((l0 + 0) == lab) ? f.x : vl;
        vl = ((l0 + 1) == lab) ? f.y : vl;
        vl = ((l0 + 2) == lab) ? f.z : vl;
        vl = ((l0 + 3) == lab) ? f.w : vl;
    }
    g_pot[gcell] = acc - v0;

    // deterministic block-reduce of gold contributions
    gred[threadIdx.x] = vl - v0;
    __syncthreads();
    #pragma unroll
    for (int s = 128; s >= 32; s >>= 1) {
        if (threadIdx.x < s) gred[threadIdx.x] += gred[threadIdx.x + s];
        __syncthreads();
    }
    if (threadIdx.x < 32) {
        float g = gred[threadIdx.x];
        #pragma unroll
        for (int off = 16; off; off >>= 1)
            g += __shfl_xor_sync(FULLMASK, g, off);
        if (threadIdx.x == 0) g_goldpart[blockIdx.x] = g;
    }
}

// ---------------------------------------------------------------------------
// Kernel 2: CKY max-plus inside pass. One CTA per batch, 128 threads.
// Charts (row stride 132 floats, 16B-aligned rows, LDS.128-phase conflict-free):
//   R[i][j]         = best score of span [i, j]           (start/row-indexed)
//   D[j][i+3]       = best score of span [i, j]           (end-indexed, +4 phys
//                     column shift so reads below share R's m alignment)
// Recurrence (thread i, width w, j = i+w):
//   R[i][j] = pot[i][j] + max_{m=i..j-1} ( R[i][m] + D[j][m+4] )
// Both operands are contiguous in m with IDENTICAL alignment -> float4 chunks
// after a <=3-element head peel; 4 accumulators break the fmax chain.
// ---------------------------------------------------------------------------
extern __shared__ float cky_smem[];

__global__ void cky_kernel(const float* __restrict__ logits,
                           const int* __restrict__ labels) {
    const int S = 132;                       // row stride in floats
    float* R = cky_smem;                     // 128*132
    float* D = cky_smem + 128 * S;           // 128*132
    float* P = cky_smem + 2 * 128 * S;       // 128*132 (pot)
    __shared__ float sh_potfix;

    int b = blockIdx.x;
    int t = threadIdx.x;
    int bcell = b * 16384;

    // length: count labels[b,0,j] != -100 (all 128 threads participate)
    int labt = labels[bcell + t];
    int len = __syncthreads_count(labt != -100);

    // preload pot into SMEM (coalesced, conflict-free)
    for (int idx = t; idx < 16384; idx += 128)
        P[(idx >> 7) * S + (idx & 127)] = g_pot[bcell + idx];

    // recompute the augmented special cell (b, 0, len-1): channel 0 gets -1e9
    if (t < 32) {
        int j = len - 1;
        int lab = labels[bcell + j];
        if (lab < 0) lab = 0;
        float v = logits[(size_t)(bcell + j) * 32 + t];
        float x = (t == lab) ? v : (v + 1.0f);
        if (t == 0) x += NEGF;
        #pragma unroll
        for (int off = 16; off; off >>= 1)
            x = fmaxf(x, __shfl_xor_sync(FULLMASK, x, off));
        float v0 = __shfl_sync(FULLMASK, v, 0);
        if (t == 0) sh_potfix = x - v0;
    }
    __syncthreads();
    if (t == 0) P[len - 1] = sh_potfix;      // row 0, col len-1
    __syncthreads();

    // width-0 init (diagonal)
    {
        float d = P[t * S + t];
        R[t * S + t] = d;
        D[t * S + t + 3] = d;                // logical D[t][t-1] at phys col t+3
    }

    for (int w = 1; w < 128; ++w) {
        __syncthreads();                     // step w-1 writes visible
        int i = t, j = i + w;
        if (j < 128) {
            const float* Ar = R + S * i;
            const float* Dr = D + S * j + 4; // phys shift: logical m -> Dr[m]
            float b0 = NEGF, b1 = NEGF, b2 = NEGF, b3 = NEGF;
            int m = i;
            int mal = (i + 3) & ~3;          // align m up to multiple of 4
            if (mal > j) mal = j;
            for (; m < mal; ++m)
                b0 = fmaxf(b0, Ar[m] + Dr[m]);
            #pragma unroll 2
            for (; m + 4 <= j; m += 4) {
                float4 a = *reinterpret_cast<const float4*>(Ar + m);
                float4 e = *reinterpret_cast<const float4*>(Dr + m);
                b0 = fmaxf(b0, a.x + e.x);
                b1 = fmaxf(b1, a.y + e.y);
                b2 = fmaxf(b2, a.z + e.z);
                b3 = fmaxf(b3, a.w + e.w);
            }
            for (; m < j; ++m)
                b0 = fmaxf(b0, Ar[m] + Dr[m]);
            float best = fmaxf(fmaxf(b0, b1), fmaxf(b2, b3));
            float v = best + P[S * i + j];
            R[S * i + j] = v;                // writes disjoint from step-w reads
            D[S * j + i + 3] = v;
        }
    }
    __syncthreads();

    // deterministic gold reduction: 64 per-block partials for this batch
    if (t < 32) {
        float g = g_goldpart[b * 64 + t] + g_goldpart[b * 64 + 32 + t];
        #pragma unroll
        for (int off = 16; off; off >>= 1)
            g += __shfl_xor_sync(FULLMASK, g, off);
        if (t == 0) {
            float pred = R[len - 1];         // R[0][len-1]
            g_margin[b] = fmaxf(pred - g, 0.0f);
        }
    }
}

// ---------------------------------------------------------------------------
// Kernel 3: mean over batches.
// ---------------------------------------------------------------------------
__global__ void mean_kernel(float* __restrict__ out) {
    int t = threadIdx.x;                     // 32 threads
    float v = g_margin[t] + g_margin[t + 32];
    #pragma unroll
    for (int off = 16; off; off >>= 1)
        v += __shfl_xor_sync(FULLMASK, v, off);
    if (t == 0) out[0] = v * (1.0f / 64.0f);
}

// ---------------------------------------------------------------------------
extern "C" void kernel_launch(void* const* d_in, const int* in_sizes, int n_in,
                              void* d_out, int out_size) {
    const float* logits = (const float*)d_in[0];   // [64,128,128,32] f32
    const int* labels   = (const int*)d_in[1];     // [64,128,128] int32
    float* out = (float*)d_out;

    (void)in_sizes; (void)n_in; (void)out_size;

    const int CKY_SMEM = 3 * 128 * 132 * (int)sizeof(float); // 202752 B
    cudaFuncSetAttribute(cky_kernel,
                         cudaFuncAttributeMaxDynamicSharedMemorySize, CKY_SMEM);

    pot_kernel<<<4096, 256>>>(logits, labels);
    cky_kernel<<<64, 128, CKY_SMEM>>>(logits, labels);
    mean_kernel<<<1, 32>>>(out);
}

// round 5
// speedup vs baseline: 3.2068x; 3.2068x over previous
#include <cuda_runtime.h>

#define NEGF (-1000000000.0f)
#define FULLMASK 0xffffffffu

// Scratch (device globals — no allocation allowed)
__device__ float g_pot[64 * 128 * 128];   // 4 MB: label/augment-maxed span potentials
__device__ float g_goldpart[4096];        // per-block gold partials (64 blocks per batch)
__device__ float g_margin[64];            // per-batch relu(pred - gold)

// ---------------------------------------------------------------------------
// Kernel 1: pot + gold partials. 8 lanes per cell.
// Lane r loads float4 r of the 128B cell -> consecutive lanes read consecutive
// 16B -> every 128B line fully consumed (4 L1 wavefronts per LDG.128, optimal).
// 3-shuffle reduce within the 8-lane group for aug-max and gold value.
// Grid: 4096 blocks x 256 threads; block handles 256 cells (32 groups x 8).
// ---------------------------------------------------------------------------
__global__ void pot_kernel(const float* __restrict__ logits,
                           const int* __restrict__ labels) {
    __shared__ float gred[256];

    int t = threadIdx.x;
    int lane = t & 31;
    int r = lane & 7;                       // lane within 8-group
    int cell0 = blockIdx.x * 256 + (t >> 3) * 8;  // first cell of this group
    const float4* lg4 = reinterpret_cast<const float4*>(logits);

    float goldacc = 0.0f;
    float mypot = 0.0f;
    #pragma unroll
    for (int n = 0; n < 8; ++n) {
        int cell = cell0 + n;
        int lab = labels[cell];
        if (lab < 0) lab = 0;               // jnp.maximum(labels, 0)
        float4 f = lg4[(size_t)cell * 8 + r];
        int l0 = r * 4;
        float a0 = f.x + (float)((l0 + 0) != lab);
        float a1 = f.y + (float)((l0 + 1) != lab);
        float a2 = f.z + (float)((l0 + 2) != lab);
        float a3 = f.w + (float)((l0 + 3) != lab);
        float acc = fmaxf(fmaxf(a0, a1), fmaxf(a2, a3));
        float cand = NEGF;
        cand = ((l0 + 0) == lab) ? f.x : cand;
        cand = ((l0 + 1) == lab) ? f.y : cand;
        cand = ((l0 + 2) == lab) ? f.z : cand;
        cand = ((l0 + 3) == lab) ? f.w : cand;
        #pragma unroll
        for (int off = 1; off <= 4; off <<= 1) {
            acc  = fmaxf(acc,  __shfl_xor_sync(FULLMASK, acc,  off));
            cand = fmaxf(cand, __shfl_xor_sync(FULLMASK, cand, off));
        }
        float v0 = __shfl_sync(FULLMASK, f.x, lane & 24);  // r==0 lane of group
        if (n == r) {                       // lane r owns cell n of its group
            mypot = acc - v0;
            goldacc += cand - v0;           // counted exactly once per cell
        }
    }
    // fully coalesced pot store: lane r -> cell0 + r
    g_pot[cell0 + r] = mypot;

    // deterministic block-reduce of gold contributions
    gred[t] = goldacc;
    __syncthreads();
    #pragma unroll
    for (int s = 128; s >= 32; s >>= 1) {
        if (t < s) gred[t] += gred[t + s];
        __syncthreads();
    }
    if (t < 32) {
        float g = gred[t];
        #pragma unroll
        for (int off = 16; off; off >>= 1)
            g += __shfl_xor_sync(FULLMASK, g, off);
        if (t == 0) g_goldpart[blockIdx.x] = g;
    }
}

// ---------------------------------------------------------------------------
// Kernel 2: CKY max-plus inside pass. One CTA per batch, 512 threads:
// 4 lanes (q=0..3) per row i = t/4. Charts (row stride S=132 floats):
//   betaS[i][w]      at R[S*i + w]
//   betaE[j][127-w]  at E[S*j + 127 - w]
// Step w, row i, j=i+w:
//   best = max_{k<w} betaS[S*i+k] + betaE[S*j + 128-w + k]
// Lane q covers k = q, q+4, q+8, ... (uniform trips, no divergence).
// Banks: (132*i + k) mod 32 = (4i + q) mod 32 -> 8 rows x 4 q = all 32 banks,
// conflict-free scalar LDS on both operands.
// ---------------------------------------------------------------------------
extern __shared__ float cky_smem[];

__global__ void cky_kernel(const float* __restrict__ logits,
                           const int* __restrict__ labels) {
    const int S = 132;
    float* R = cky_smem;                    // betaS: 128*S
    float* E = cky_smem + 128 * S;          // betaE: 128*S
    float* P = cky_smem + 256 * S;          // pot:   128*S
    __shared__ float sh_potfix;

    int b = blockIdx.x;
    int t = threadIdx.x;
    int i = t >> 2;                         // row 0..127
    int q = t & 3;                          // lane within row group
    int bcell = b * 16384;

    // length: count labels[b,0,j] != -100 (first 128 threads contribute)
    int haslab = (t < 128) ? (labels[bcell + t] != -100) : 0;
    int len = __syncthreads_count(haslab);

    // preload pot into SMEM (coalesced, conflict-free)
    for (int idx = t; idx < 16384; idx += 512)
        P[(idx >> 7) * S + (idx & 127)] = g_pot[bcell + idx];

    // recompute the augmented special cell (b, 0, len-1): channel 0 gets -1e9
    if (t < 32) {
        int j = len - 1;
        int lab = labels[bcell + j];
        if (lab < 0) lab = 0;
        float v = logits[(size_t)(bcell + j) * 32 + t];
        float x = (t == lab) ? v : (v + 1.0f);
        if (t == 0) x += NEGF;
        #pragma unroll
        for (int off = 16; off; off >>= 1)
            x = fmaxf(x, __shfl_xor_sync(FULLMASK, x, off));
        float v0 = __shfl_sync(FULLMASK, v, 0);
        if (t == 0) sh_potfix = x - v0;
    }
    __syncthreads();
    if (t == 0) P[len - 1] = sh_potfix;     // row 0, col len-1
    __syncthreads();

    // width-0 init (diagonal)
    if (q == 0) {
        float d = P[i * S + i];
        R[i * S] = d;                       // betaS[i][0]
        E[i * S + 127] = d;                 // betaE[i][127]
    }

    for (int w = 1; w < 128; ++w) {
        __syncthreads();                    // step w-1 writes visible
        int j = i + w;
        float best = NEGF;
        if (j < 128) {
            const float* A  = R + S * i;
            const float* Ee = E + S * j + (128 - w);
            int k = q;
            for (; k + 12 < w; k += 16) {   // 4x unroll: 8 batched LDS
                float x0 = A[k]      + Ee[k];
                float x1 = A[k + 4]  + Ee[k + 4];
                float x2 = A[k + 8]  + Ee[k + 8];
                float x3 = A[k + 12] + Ee[k + 12];
                best = fmaxf(best, fmaxf(fmaxf(x0, x1), fmaxf(x2, x3)));
            }
            for (; k < w; k += 4)
                best = fmaxf(best, A[k] + Ee[k]);
        }
        // all 512 threads reach these uniformly
        best = fmaxf(best, __shfl_xor_sync(FULLMASK, best, 1));
        best = fmaxf(best, __shfl_xor_sync(FULLMASK, best, 2));
        if (j < 128 && q == 0) {
            float v = best + P[S * i + i + w];
            R[S * i + w] = v;               // betaS[i][w]
            E[S * j + 127 - w] = v;         // betaE[j][127-w]
        }
    }
    __syncthreads();

    // deterministic gold reduction: 64 per-block partials for this batch
    if (t < 32) {
        float g = g_goldpart[b * 64 + t] + g_goldpart[b * 64 + 32 + t];
        #pragma unroll
        for (int off = 16; off; off >>= 1)
            g += __shfl_xor_sync(FULLMASK, g, off);
        if (t == 0) {
            float pred = R[len - 1];        // betaS[0][len-1]
            g_margin[b] = fmaxf(pred - g, 0.0f);
        }
    }
}

// ---------------------------------------------------------------------------
// Kernel 3: mean over batches.
// ---------------------------------------------------------------------------
__global__ void mean_kernel(float* __restrict__ out) {
    int t = threadIdx.x;                    // 32 threads
    float v = g_margin[t] + g_margin[t + 32];
    #pragma unroll
    for (int off = 16; off; off >>= 1)
        v += __shfl_xor_sync(FULLMASK, v, off);
    if (t == 0) out[0] = v * (1.0f / 64.0f);
}

// ---------------------------------------------------------------------------
extern "C" void kernel_launch(void* const* d_in, const int* in_sizes, int n_in,
                              void* d_out, int out_size) {
    const float* logits = (const float*)d_in[0];   // [64,128,128,32] f32
    const int* labels   = (const int*)d_in[1];     // [64,128,128] int32
    float* out = (float*)d_out;

    (void)in_sizes; (void)n_in; (void)out_size;

    const int CKY_SMEM = 3 * 128 * 132 * (int)sizeof(float); // 202752 B
    cudaFuncSetAttribute(cky_kernel,
                         cudaFuncAttributeMaxDynamicSharedMemorySize, CKY_SMEM);

    pot_kernel<<<4096, 256>>>(logits, labels);
    cky_kernel<<<64, 512, CKY_SMEM>>>(logits, labels);
    mean_kernel<<<1, 32>>>(out);
}